// round 13
// baseline (speedup 1.0000x reference)
#include <cuda_runtime.h>
#include <cuda_bf16.h>
#include <float.h>
#include <stdint.h>

#define D_DIM   768
#define NREL    128
#define MAXM    32
#define KC      32        // K chunk (f32 elems)
#define NCH     24        // D_DIM / KC
#define TROWS   64        // rows per CTA (phase A)
#define NTA     256
#define NTB     256
#define BP      132
#define PITCH   40        // smem row pitch in bf16 (80B): ldmatrix conflict-free

__device__ float g_att[16384 * NREL];           // 8 MB scratch
__device__ __nv_bfloat16 g_wh[NREL * D_DIM];    // W hi (L2-resident)
__device__ __nv_bfloat16 g_wl[NREL * D_DIM];    // W lo

// smem (dynamic) layout for gemm, element offsets
#define A_BUF   (TROWS * PITCH)         // 2560
#define B_BUF   (NREL * PITCH)          // 5120
#define SMEM_A_ELE (2 * A_BUF)
#define SMEM_B_ELE (2 * B_BUF)
#define SMEM_GEMM ((2 * SMEM_A_ELE + 2 * SMEM_B_ELE) * 2)   // bytes = 61440

// ---- helpers ----
__device__ __forceinline__ uint32_t bfsplit2(float a, float b, uint32_t& lo) {
    __nv_bfloat16 ha = __float2bfloat16_rn(a), hb = __float2bfloat16_rn(b);
    __nv_bfloat16 la = __float2bfloat16_rn(a - __bfloat162float(ha));
    __nv_bfloat16 lb = __float2bfloat16_rn(b - __bfloat162float(hb));
    lo = ((uint32_t)__bfloat16_as_ushort(lb) << 16) | __bfloat16_as_ushort(la);
    return ((uint32_t)__bfloat16_as_ushort(hb) << 16) | __bfloat16_as_ushort(ha);
}
__device__ __forceinline__ void cvt8(float4 x, float4 y, uint4& H, uint4& L) {
    H.x = bfsplit2(x.x, x.y, L.x);
    H.y = bfsplit2(x.z, x.w, L.y);
    H.z = bfsplit2(y.x, y.y, L.z);
    H.w = bfsplit2(y.z, y.w, L.w);
}
__device__ __forceinline__ void ldm4(uint32_t* r, uint32_t addr) {
    asm volatile("ldmatrix.sync.aligned.m8n8.x4.shared.b16 {%0,%1,%2,%3}, [%4];"
        : "=r"(r[0]), "=r"(r[1]), "=r"(r[2]), "=r"(r[3]) : "r"(addr));
}
__device__ __forceinline__ void mma16816(float* c, const uint32_t* a, uint32_t b0, uint32_t b1) {
    asm volatile("mma.sync.aligned.m16n8k16.row.col.f32.bf16.bf16.f32 "
        "{%0,%1,%2,%3}, {%4,%5,%6,%7}, {%8,%9}, {%0,%1,%2,%3};"
        : "+f"(c[0]), "+f"(c[1]), "+f"(c[2]), "+f"(c[3])
        : "r"(a[0]), "r"(a[1]), "r"(a[2]), "r"(a[3]), "r"(b0), "r"(b1));
}

// ---------------- W pre-convert: f32 -> bf16 hi/lo ----------------
__global__ void convert_w_kernel(const float* __restrict__ W) {
    const int i = blockIdx.x * 128 + threadIdx.x;   // 49152 threads x 1 float2
    const float2 v = reinterpret_cast<const float2*>(W)[i];
    uint32_t l;
    const uint32_t h = bfsplit2(v.x, v.y, l);
    reinterpret_cast<uint32_t*>(g_wh)[i] = h;
    reinterpret_cast<uint32_t*>(g_wl)[i] = l;
}

// ---------------- Phase A: att = rep @ W^T via mma.sync bf16 hi/lo split ----------------
__global__ __launch_bounds__(NTA)
void gemm_att_mma(const float* __restrict__ rep, int nsum)
{
    extern __shared__ __align__(16) char smraw[];
    __nv_bfloat16* AHs = reinterpret_cast<__nv_bfloat16*>(smraw);
    __nv_bfloat16* ALs = AHs + SMEM_A_ELE;
    __nv_bfloat16* BHs = ALs + SMEM_A_ELE;
    __nv_bfloat16* BLs = BHs + SMEM_B_ELE;

    const int t    = threadIdx.x;
    const int lane = t & 31;
    const int w    = t >> 5;
    const int rb   = w >> 1;          // row-block (0..3)
    const int nh   = w & 1;           // N half
    const int row0 = blockIdx.x * TROWS;

    // global-load mapping: A 8 floats/thread, B 16 bf16/thread (per H/L)
    const int ar = t >> 2, ac = (t & 3) * 8;
    const float* ap = rep + (size_t)min(row0 + ar, nsum - 1) * D_DIM + ac;
    const int br = t >> 1, bc = (t & 1) * 16;
    const __nv_bfloat16* bhp = g_wh + (size_t)br * D_DIM + bc;
    const __nv_bfloat16* blp = g_wl + (size_t)br * D_DIM + bc;

    const uint32_t aoff = (uint32_t)(((16 * rb + (lane & 15)) * PITCH + ((lane >> 4) << 3)) * 2);
    const uint32_t boff = (uint32_t)(((nh * 64 + (lane & 7) + ((lane >> 4) << 3)) * PITCH + (lane & 8)) * 2);
    uint32_t ahA[2], alA[2], bhA[2], blA[2];
#pragma unroll
    for (int q = 0; q < 2; ++q) {
        ahA[q] = (uint32_t)__cvta_generic_to_shared(AHs + q * A_BUF) + aoff;
        alA[q] = (uint32_t)__cvta_generic_to_shared(ALs + q * A_BUF) + aoff;
        bhA[q] = (uint32_t)__cvta_generic_to_shared(BHs + q * B_BUF) + boff;
        blA[q] = (uint32_t)__cvta_generic_to_shared(BLs + q * B_BUF) + boff;
    }

    float acc[8][4];
#pragma unroll
    for (int n = 0; n < 8; ++n)
#pragma unroll
        for (int q = 0; q < 4; ++q) acc[n][q] = 0.f;

    // prefetch chunk 0 -> buffer 0
    float4 pa0 = *(const float4*)ap;
    float4 pa1 = *(const float4*)(ap + 4);
    uint4  ph0 = *(const uint4*)bhp;
    uint4  ph1 = *(const uint4*)(bhp + 8);
    uint4  pl0 = *(const uint4*)blp;
    uint4  pl1 = *(const uint4*)(blp + 8);
    {
        uint4 H, L;
        cvt8(pa0, pa1, H, L);
        *(uint4*)&AHs[ar * PITCH + ac] = H;
        *(uint4*)&ALs[ar * PITCH + ac] = L;
        *(uint4*)&BHs[br * PITCH + bc] = ph0;
        *(uint4*)&BHs[br * PITCH + bc + 8] = ph1;
        *(uint4*)&BLs[br * PITCH + bc] = pl0;
        *(uint4*)&BLs[br * PITCH + bc + 8] = pl1;
    }
    __syncthreads();

    for (int c = 0; c < NCH; ++c) {
        const int cur = c & 1;
        if (c + 1 < NCH) {              // prefetch next chunk (hidden under MMAs)
            const int cc = (c + 1) * KC;
            pa0 = *(const float4*)(ap + cc);
            pa1 = *(const float4*)(ap + cc + 4);
            ph0 = *(const uint4*)(bhp + cc);
            ph1 = *(const uint4*)(bhp + cc + 8);
            pl0 = *(const uint4*)(blp + cc);
            pl1 = *(const uint4*)(blp + cc + 8);
        }
        // compute from buffer cur: 2 k-steps x 4 p-tiles x 6 MMA
#pragma unroll
        for (int s = 0; s < 2; ++s) {
            uint32_t AH[4], AL[4];
            ldm4(AH, ahA[cur] + s * 32);
            ldm4(AL, alA[cur] + s * 32);
#pragma unroll
            for (int p = 0; p < 4; ++p) {
                uint32_t BH[4], BL[4];
                ldm4(BH, bhA[cur] + p * (16 * PITCH * 2) + s * 32);
                ldm4(BL, blA[cur] + p * (16 * PITCH * 2) + s * 32);
                mma16816(acc[2 * p],     AH, BH[0], BH[1]);
                mma16816(acc[2 * p],     AH, BL[0], BL[1]);
                mma16816(acc[2 * p],     AL, BH[0], BH[1]);
                mma16816(acc[2 * p + 1], AH, BH[2], BH[3]);
                mma16816(acc[2 * p + 1], AH, BL[2], BL[3]);
                mma16816(acc[2 * p + 1], AL, BH[2], BH[3]);
            }
        }
        if (c + 1 < NCH) {              // store next chunk into other buffer
            const int nb = (cur ^ 1);
            uint4 H, L;
            cvt8(pa0, pa1, H, L);
            *(uint4*)&AHs[nb * A_BUF + ar * PITCH + ac] = H;
            *(uint4*)&ALs[nb * A_BUF + ar * PITCH + ac] = L;
            *(uint4*)&BHs[nb * B_BUF + br * PITCH + bc] = ph0;
            *(uint4*)&BHs[nb * B_BUF + br * PITCH + bc + 8] = ph1;
            *(uint4*)&BLs[nb * B_BUF + br * PITCH + bc] = pl0;
            *(uint4*)&BLs[nb * B_BUF + br * PITCH + bc + 8] = pl1;
        }
        __syncthreads();
    }

    // writeback
    const int orow = row0 + 16 * rb + (lane >> 2);
    float* gp = g_att + (size_t)orow * NREL + nh * 64 + 2 * (lane & 3);
    if (orow < nsum) {
#pragma unroll
        for (int nt = 0; nt < 8; ++nt)
            *(float2*)(gp + 8 * nt) = make_float2(acc[nt][0], acc[nt][1]);
    }
    if (orow + 8 < nsum) {
        float* gp1 = gp + 8 * NREL;
#pragma unroll
        for (int nt = 0; nt < 8; ++nt)
            *(float2*)(gp1 + 8 * nt) = make_float2(acc[nt][2], acc[nt][3]);
    }
}

// ---------------- Phase B: per-bag softmax chain (two-pass, occ-3) ----------------
__global__ __launch_bounds__(NTB, 3)
void bag_softmax_kernel(const float* __restrict__ bias,
                        const int*   __restrict__ scope,
                        float*       __restrict__ out)
{
    __shared__ float attS[MAXM][BP];
    __shared__ float smS[MAXM][BP];
    __shared__ float biasS[NREL];

    const int b = blockIdx.x;
    const int t = threadIdx.x;

    const int start = scope[2 * b];
    int m = scope[2 * b + 1] - start;
    if (m > MAXM) m = MAXM;

    if (t >= 128 && t < 256) biasS[t - 128] = bias[t - 128];

    const int tot4 = m * (NREL / 4);
    for (int idx = t; idx < tot4; idx += NTB) {
        const int j   = idx >> 5;
        const int col = (idx & 31) * 4;
        *reinterpret_cast<float4*>(&attS[j][col]) =
            *reinterpret_cast<const float4*>(&g_att[(size_t)(start + j) * NREL + col]);
    }
    __syncthreads();

    // B1: column softmax over j (thread-per-n)
    if (t < NREL) {
        const int n = t;
        float mx = -FLT_MAX;
        for (int j = 0; j < m; ++j) mx = fmaxf(mx, attS[j][n]);
        float ssum = 0.f;
        for (int j = 0; j < m; ++j) {
            const float e = __expf(attS[j][n] - mx);
            smS[j][n] = e;
            ssum += e;
        }
        const float inv = 1.f / ssum;
        for (int j = 0; j < m; ++j) smS[j][n] *= inv;
    }
    __syncthreads();

    const int tn = t >> 4;
    const int tk = t & 15;
    const float4 bb0 = *reinterpret_cast<const float4*>(&biasS[tk * 4]);
    const float4 bb1 = *reinterpret_cast<const float4*>(&biasS[64 + tk * 4]);

    // two passes over n-halves: pass covers n = 4tn + 64*pass + i
#pragma unroll
    for (int pass = 0; pass < 2; ++pass) {
        float fa[4][2][4];
#pragma unroll
        for (int i = 0; i < 4; ++i)
#pragma unroll
            for (int uk = 0; uk < 2; ++uk)
#pragma unroll
                for (int jv = 0; jv < 4; ++jv) fa[i][uk][jv] = 0.f;

#pragma unroll 2
        for (int j = 0; j < m; ++j) {
            const float4 s = *reinterpret_cast<const float4*>(&smS[j][64 * pass + tn * 4]);
            const float4 a0 = *reinterpret_cast<const float4*>(&attS[j][tk * 4]);
            const float4 a1 = *reinterpret_cast<const float4*>(&attS[j][64 + tk * 4]);
            const float sv[4] = {s.x, s.y, s.z, s.w};
            const float av[2][4] = {{a0.x, a0.y, a0.z, a0.w}, {a1.x, a1.y, a1.z, a1.w}};
#pragma unroll
            for (int i = 0; i < 4; ++i)
#pragma unroll
                for (int uk = 0; uk < 2; ++uk)
#pragma unroll
                    for (int jv = 0; jv < 4; ++jv)
                        fa[i][uk][jv] = fmaf(sv[i], av[uk][jv], fa[i][uk][jv]);
        }

        const float bv[2][4] = {{bb0.x, bb0.y, bb0.z, bb0.w}, {bb1.x, bb1.y, bb1.z, bb1.w}};
#pragma unroll
        for (int i = 0; i < 4; ++i)
#pragma unroll
            for (int uk = 0; uk < 2; ++uk)
#pragma unroll
                for (int jv = 0; jv < 4; ++jv) fa[i][uk][jv] += bv[uk][jv];

        // row softmax over k (16 threads sharing tn), emit diagonal
#pragma unroll
        for (int i = 0; i < 4; ++i) {
            float mx = -FLT_MAX;
#pragma unroll
            for (int uk = 0; uk < 2; ++uk)
#pragma unroll
                for (int jv = 0; jv < 4; ++jv) mx = fmaxf(mx, fa[i][uk][jv]);
#pragma unroll
            for (int o = 8; o; o >>= 1) mx = fmaxf(mx, __shfl_xor_sync(0xffffffffu, mx, o));
            float es = 0.f;
            float ev[2][4];
#pragma unroll
            for (int uk = 0; uk < 2; ++uk)
#pragma unroll
                for (int jv = 0; jv < 4; ++jv) {
                    ev[uk][jv] = __expf(fa[i][uk][jv] - mx);
                    es += ev[uk][jv];
                }
#pragma unroll
            for (int o = 8; o; o >>= 1) es += __shfl_xor_sync(0xffffffffu, es, o);
            if (tk == tn) {
                const int n = tn * 4 + 64 * pass + i;   // diag: uk==pass, jv==i
                out[(size_t)b * NREL + n] = ev[pass][i] / es;
            }
        }
    }
}

extern "C" void kernel_launch(void* const* d_in, const int* in_sizes, int n_in,
                              void* d_out, int out_size)
{
    (void)n_in; (void)out_size;
    const float* rep   = (const float*)d_in[0];
    const float* W     = (const float*)d_in[1];
    const float* bias  = (const float*)d_in[2];
    const int*   scope = (const int*)d_in[3];
    float* out = (float*)d_out;

    const int nsum = in_sizes[0] / D_DIM;
    const int B    = in_sizes[3] / 2;

    static int attr_set = 0;
    if (!attr_set) {
        cudaFuncSetAttribute(gemm_att_mma,
                             cudaFuncAttributeMaxDynamicSharedMemorySize, SMEM_GEMM);
        attr_set = 1;
    }

    convert_w_kernel<<<(NREL * D_DIM / 2 + 127) / 128, 128>>>(W);
    const int gridA = (nsum + TROWS - 1) / TROWS;
    gemm_att_mma<<<gridA, NTA, SMEM_GEMM>>>(rep, nsum);
    bag_softmax_kernel<<<B, NTB>>>(bias, scope, out);
}

// round 14
// speedup vs baseline: 1.6979x; 1.6979x over previous
#include <cuda_runtime.h>
#include <cuda_bf16.h>
#include <float.h>
#include <stdint.h>

#define D_DIM   768
#define NREL    128
#define MAXM    32
#define NCH     48        // K chunks of 16
#define TROWS   64        // rows per CTA (phase A)
#define NTA     256
#define NTB     256
#define BP      132
#define PITCH   24        // smem row pitch in bf16 (48B): ldmatrix conflict-free

__device__ float g_att[16384 * NREL];           // 8 MB scratch
__device__ __nv_bfloat16 g_wh[NREL * D_DIM];    // W hi (L2-resident)
__device__ __nv_bfloat16 g_wl[NREL * D_DIM];    // W lo

// ---- helpers ----
__device__ __forceinline__ uint32_t bfsplit2(float a, float b, uint32_t& lo) {
    __nv_bfloat16 ha = __float2bfloat16_rn(a), hb = __float2bfloat16_rn(b);
    __nv_bfloat16 la = __float2bfloat16_rn(a - __bfloat162float(ha));
    __nv_bfloat16 lb = __float2bfloat16_rn(b - __bfloat162float(hb));
    lo = ((uint32_t)__bfloat16_as_ushort(lb) << 16) | __bfloat16_as_ushort(la);
    return ((uint32_t)__bfloat16_as_ushort(hb) << 16) | __bfloat16_as_ushort(ha);
}
__device__ __forceinline__ void ldm4(uint32_t* r, uint32_t addr) {
    asm volatile("ldmatrix.sync.aligned.m8n8.x4.shared.b16 {%0,%1,%2,%3}, [%4];"
        : "=r"(r[0]), "=r"(r[1]), "=r"(r[2]), "=r"(r[3]) : "r"(addr));
}
__device__ __forceinline__ void mma16816(float* c, const uint32_t* a, uint32_t b0, uint32_t b1) {
    asm volatile("mma.sync.aligned.m16n8k16.row.col.f32.bf16.bf16.f32 "
        "{%0,%1,%2,%3}, {%4,%5,%6,%7}, {%8,%9}, {%0,%1,%2,%3};"
        : "+f"(c[0]), "+f"(c[1]), "+f"(c[2]), "+f"(c[3])
        : "r"(a[0]), "r"(a[1]), "r"(a[2]), "r"(a[3]), "r"(b0), "r"(b1));
}

// ---------------- W pre-convert: f32 -> bf16 hi/lo (round-8 measured version) ----------------
__global__ void convert_w_kernel(const float* __restrict__ W) {
    const int i = blockIdx.x * 256 + threadIdx.x;   // 24576 threads x 4 floats
    const float4 v = reinterpret_cast<const float4*>(W)[i];
    uint2 h, l;
    h.x = bfsplit2(v.x, v.y, l.x);
    h.y = bfsplit2(v.z, v.w, l.y);
    reinterpret_cast<uint2*>(g_wh)[i] = h;
    reinterpret_cast<uint2*>(g_wl)[i] = l;
}

// ---------------- Phase A: att = rep @ W^T via mma.sync (round-8 measured version) ----------------
__global__ __launch_bounds__(NTA)
void gemm_att_mma(const float* __restrict__ rep, int nsum)
{
    __shared__ __align__(16) __nv_bfloat16 AHs[2][TROWS][PITCH];
    __shared__ __align__(16) __nv_bfloat16 ALs[2][TROWS][PITCH];
    __shared__ __align__(16) __nv_bfloat16 BHs[2][NREL][PITCH];
    __shared__ __align__(16) __nv_bfloat16 BLs[2][NREL][PITCH];

    const int t    = threadIdx.x;
    const int lane = t & 31;
    const int w    = t >> 5;
    const int rb   = w >> 1;          // row-block (0..3): rows 16rb..16rb+15
    const int nh   = w & 1;           // N half (0..1): cols nh*64..+63
    const int row0 = blockIdx.x * TROWS;

    // global-load mapping
    const int ar = t >> 2;                      // A row 0..63
    const int ac = (t & 3) * 4;                 // A col group
    const float* ap = rep + (size_t)min(row0 + ar, nsum - 1) * D_DIM + ac;
    const int br = t >> 1;                      // B row 0..127
    const int bc = (t & 1) * 8;                 // B col group (8 bf16)
    const __nv_bfloat16* bhp = g_wh + (size_t)br * D_DIM + bc;
    const __nv_bfloat16* blp = g_wl + (size_t)br * D_DIM + bc;

    // ldmatrix lane addresses (per buffer)
    const uint32_t aoff = (uint32_t)(((16 * rb + (lane & 15)) * PITCH + ((lane >> 4) << 3)) * 2);
    const uint32_t boff = (uint32_t)(((nh * 64 + (lane & 7) + ((lane >> 4) << 3)) * PITCH + (lane & 8)) * 2);
    uint32_t ahA[2], alA[2], bhA[2], blA[2];
#pragma unroll
    for (int q = 0; q < 2; ++q) {
        ahA[q] = (uint32_t)__cvta_generic_to_shared(&AHs[q][0][0]) + aoff;
        alA[q] = (uint32_t)__cvta_generic_to_shared(&ALs[q][0][0]) + aoff;
        bhA[q] = (uint32_t)__cvta_generic_to_shared(&BHs[q][0][0]) + boff;
        blA[q] = (uint32_t)__cvta_generic_to_shared(&BLs[q][0][0]) + boff;
    }

    float acc[8][4];
#pragma unroll
    for (int n = 0; n < 8; ++n)
#pragma unroll
        for (int q = 0; q < 4; ++q) acc[n][q] = 0.f;

    // prefetch chunk 0 and store to buffer 0
    float4 pa = *(const float4*)ap;
    uint4  pbh = *(const uint4*)bhp;
    uint4  pbl = *(const uint4*)blp;
    {
        uint2 h, l;
        h.x = bfsplit2(pa.x, pa.y, l.x);
        h.y = bfsplit2(pa.z, pa.w, l.y);
        *(uint2*)&AHs[0][ar][ac] = h;
        *(uint2*)&ALs[0][ar][ac] = l;
        *(uint4*)&BHs[0][br][bc] = pbh;
        *(uint4*)&BLs[0][br][bc] = pbl;
    }
    __syncthreads();

    for (int c = 0; c < NCH; ++c) {
        const int cur = c & 1;
        // prefetch next chunk (globals) — overlapped with MMAs below
        if (c + 1 < NCH) {
            const int cc = (c + 1) * 16;
            pa  = *(const float4*)(ap + cc);
            pbh = *(const uint4*)(bhp + cc);
            pbl = *(const uint4*)(blp + cc);
        }
        // compute from buffer cur
        uint32_t AH[4], AL[4];
        ldm4(AH, ahA[cur]);
        ldm4(AL, alA[cur]);
#pragma unroll
        for (int p = 0; p < 4; ++p) {
            uint32_t BH[4], BL[4];
            ldm4(BH, bhA[cur] + p * (16 * PITCH * 2));
            ldm4(BL, blA[cur] + p * (16 * PITCH * 2));
            mma16816(acc[2 * p],     AH, BH[0], BH[1]);
            mma16816(acc[2 * p],     AH, BL[0], BL[1]);
            mma16816(acc[2 * p],     AL, BH[0], BH[1]);
            mma16816(acc[2 * p + 1], AH, BH[2], BH[3]);
            mma16816(acc[2 * p + 1], AH, BL[2], BL[3]);
            mma16816(acc[2 * p + 1], AL, BH[2], BH[3]);
        }
        // store next chunk into the other buffer
        if (c + 1 < NCH) {
            const int nb = cur ^ 1;
            uint2 h, l;
            h.x = bfsplit2(pa.x, pa.y, l.x);
            h.y = bfsplit2(pa.z, pa.w, l.y);
            *(uint2*)&AHs[nb][ar][ac] = h;
            *(uint2*)&ALs[nb][ar][ac] = l;
            *(uint4*)&BHs[nb][br][bc] = pbh;
            *(uint4*)&BLs[nb][br][bc] = pbl;
        }
        __syncthreads();
    }

    // writeback
    const int orow = row0 + 16 * rb + (lane >> 2);
    float* gp = g_att + (size_t)orow * NREL + nh * 64 + 2 * (lane & 3);
    if (orow < nsum) {
#pragma unroll
        for (int nt = 0; nt < 8; ++nt)
            *(float2*)(gp + 8 * nt) = make_float2(acc[nt][0], acc[nt][1]);
    }
    if (orow + 8 < nsum) {
        float* gp1 = gp + 8 * NREL;
#pragma unroll
        for (int nt = 0; nt < 8; ++nt)
            *(float2*)(gp1 + 8 * nt) = make_float2(acc[nt][2], acc[nt][3]);
    }
}

// ---------------- Phase B: per-bag softmax chain (two-pass, occ-3 — the ONE change under test) ----------------
__global__ __launch_bounds__(NTB, 3)
void bag_softmax_kernel(const float* __restrict__ bias,
                        const int*   __restrict__ scope,
                        float*       __restrict__ out)
{
    __shared__ float attS[MAXM][BP];
    __shared__ float smS[MAXM][BP];
    __shared__ float biasS[NREL];

    const int b = blockIdx.x;
    const int t = threadIdx.x;

    const int start = scope[2 * b];
    int m = scope[2 * b + 1] - start;
    if (m > MAXM) m = MAXM;

    if (t >= 128 && t < 256) biasS[t - 128] = bias[t - 128];

    const int tot4 = m * (NREL / 4);
    for (int idx = t; idx < tot4; idx += NTB) {
        const int j   = idx >> 5;
        const int col = (idx & 31) * 4;
        *reinterpret_cast<float4*>(&attS[j][col]) =
            *reinterpret_cast<const float4*>(&g_att[(size_t)(start + j) * NREL + col]);
    }
    __syncthreads();

    // B1: column softmax over j (thread-per-n)
    if (t < NREL) {
        const int n = t;
        float mx = -FLT_MAX;
        for (int j = 0; j < m; ++j) mx = fmaxf(mx, attS[j][n]);
        float ssum = 0.f;
        for (int j = 0; j < m; ++j) {
            const float e = __expf(attS[j][n] - mx);
            smS[j][n] = e;
            ssum += e;
        }
        const float inv = 1.f / ssum;
        for (int j = 0; j < m; ++j) smS[j][n] *= inv;
    }
    __syncthreads();

    const int tn = t >> 4;
    const int tk = t & 15;
    const float4 bb0 = *reinterpret_cast<const float4*>(&biasS[tk * 4]);
    const float4 bb1 = *reinterpret_cast<const float4*>(&biasS[64 + tk * 4]);

    // two passes over n-halves: pass covers n = 4tn + 64*pass + i
#pragma unroll
    for (int pass = 0; pass < 2; ++pass) {
        float fa[4][2][4];
#pragma unroll
        for (int i = 0; i < 4; ++i)
#pragma unroll
            for (int uk = 0; uk < 2; ++uk)
#pragma unroll
                for (int jv = 0; jv < 4; ++jv) fa[i][uk][jv] = 0.f;

#pragma unroll 2
        for (int j = 0; j < m; ++j) {
            const float4 s  = *reinterpret_cast<const float4*>(&smS[j][64 * pass + tn * 4]);
            const float4 a0 = *reinterpret_cast<const float4*>(&attS[j][tk * 4]);
            const float4 a1 = *reinterpret_cast<const float4*>(&attS[j][64 + tk * 4]);
            const float sv[4] = {s.x, s.y, s.z, s.w};
            const float av[2][4] = {{a0.x, a0.y, a0.z, a0.w}, {a1.x, a1.y, a1.z, a1.w}};
#pragma unroll
            for (int i = 0; i < 4; ++i)
#pragma unroll
                for (int uk = 0; uk < 2; ++uk)
#pragma unroll
                    for (int jv = 0; jv < 4; ++jv)
                        fa[i][uk][jv] = fmaf(sv[i], av[uk][jv], fa[i][uk][jv]);
        }

        const float bv[2][4] = {{bb0.x, bb0.y, bb0.z, bb0.w}, {bb1.x, bb1.y, bb1.z, bb1.w}};
#pragma unroll
        for (int i = 0; i < 4; ++i)
#pragma unroll
            for (int uk = 0; uk < 2; ++uk)
#pragma unroll
                for (int jv = 0; jv < 4; ++jv) fa[i][uk][jv] += bv[uk][jv];

        // row softmax over k (16 threads sharing tn), emit diagonal
#pragma unroll
        for (int i = 0; i < 4; ++i) {
            float mx = -FLT_MAX;
#pragma unroll
            for (int uk = 0; uk < 2; ++uk)
#pragma unroll
                for (int jv = 0; jv < 4; ++jv) mx = fmaxf(mx, fa[i][uk][jv]);
#pragma unroll
            for (int o = 8; o; o >>= 1) mx = fmaxf(mx, __shfl_xor_sync(0xffffffffu, mx, o));
            float es = 0.f;
            float ev[2][4];
#pragma unroll
            for (int uk = 0; uk < 2; ++uk)
#pragma unroll
                for (int jv = 0; jv < 4; ++jv) {
                    ev[uk][jv] = __expf(fa[i][uk][jv] - mx);
                    es += ev[uk][jv];
                }
#pragma unroll
            for (int o = 8; o; o >>= 1) es += __shfl_xor_sync(0xffffffffu, es, o);
            if (tk == tn) {
                const int n = tn * 4 + 64 * pass + i;   // diag: uk==pass, jv==i
                out[(size_t)b * NREL + n] = ev[pass][i] / es;
            }
        }
    }
}

extern "C" void kernel_launch(void* const* d_in, const int* in_sizes, int n_in,
                              void* d_out, int out_size)
{
    (void)n_in; (void)out_size;
    const float* rep   = (const float*)d_in[0];
    const float* W     = (const float*)d_in[1];
    const float* bias  = (const float*)d_in[2];
    const int*   scope = (const int*)d_in[3];
    float* out = (float*)d_out;

    const int nsum = in_sizes[0] / D_DIM;
    const int B    = in_sizes[3] / 2;

    convert_w_kernel<<<(NREL * D_DIM / 4 + 255) / 256, 256>>>(W);
    const int gridA = (nsum + TROWS - 1) / TROWS;
    gemm_att_mma<<<gridA, NTA>>>(rep, nsum);
    bag_softmax_kernel<<<B, NTB>>>(bias, scope, out);
}